// round 4
// baseline (speedup 1.0000x reference)
#include <cuda_runtime.h>
#include <cuda_bf16.h>
#include <cstdint>

// EmbeddingBagCollection: F=8 tables [N=200000, D=64] f32, values [F, T=163840] i32,
// offsets [F, B+1=8193] i32. Output [B=8192, F*D=512] f32.
//
// Balanced index-space partition: each warp owns exactly 32 consecutive jagged
// indices of one feature (F*T/32 = 40960 identical warps).
//  - 32 indices in one coalesced LDG; bag ids via binary search on offsets
//    (L1-resident, independent of index data -> overlaps row loads).
//  - Half-warp pair loading: 2 rows per LDG.128, all 16 issued up front
//    -> 16 rows (8 KB) in flight per warp.
//  - Segmented register accumulation; atomicAdd flush only at bag boundaries.
//  - Pre-kernel zeroes the output (empty bags pool to zero).

static constexpr int F = 8;
static constexpr int B = 8192;
static constexpr int N = 200000;
static constexpr int D = 64;
static constexpr int T = 163840;
static constexpr int WPF = T / 32;          // warps per feature = 5120
static constexpr unsigned FULL = 0xffffffffu;

__global__ __launch_bounds__(512)
void ebc_zero_kernel(float4* __restrict__ out, int n4)
{
    const int i = blockIdx.x * blockDim.x + threadIdx.x;
    if (i < n4) out[i] = make_float4(0.f, 0.f, 0.f, 0.f);
}

__global__ __launch_bounds__(256, 2)
void ebc_gather_kernel(const float* __restrict__ tables,
                       const int*   __restrict__ values,
                       const int*   __restrict__ offsets,
                       float*       __restrict__ out)
{
    const int gwarp = (blockIdx.x * blockDim.x + threadIdx.x) >> 5;
    const int lane  = threadIdx.x & 31;

    const int f    = gwarp / WPF;
    const int base = (gwarp - f * WPF) * 32;
    const int half = lane >> 4;             // 0: even positions, 1: odd
    const int hl   = lane & 15;             // float4 slot within a row
    const int pos  = base + lane;           // this lane's jagged index position

    // Coalesced index load (DRAM) — issued first, consumed after the search.
    const int idx = __ldg(values + (size_t)f * T + pos);

    // Bag id for `pos`: first b with offsets[b+1] > pos. Pure function of pos,
    // runs while idx/table loads are in flight. 14 predicated steps cover B=8192.
    const int* __restrict__ offs1 = offsets + f * (B + 1) + 1;
    int lo = 0, hi = B;
#pragma unroll
    for (int it = 0; it < 14; ++it) {
        if (lo < hi) {
            const int mid = (lo + hi) >> 1;
            if (__ldg(offs1 + mid) <= pos) lo = mid + 1; else hi = mid;
        }
    }
    const int seg = lo;

    // Issue all 16 pair-loads (each LDG.128 fetches 2 full 256B rows warp-wide).
    const float4* __restrict__ tab4 =
        reinterpret_cast<const float4*>(tables + (size_t)f * (N * D));
    float4 v[16];
#pragma unroll
    for (int p = 0; p < 16; ++p) {
        const int r = __shfl_sync(FULL, idx, 2 * p + half);
        v[p] = __ldg(tab4 + (size_t)r * (D / 4) + hl);
    }

    // Segmented accumulation over this half-lane's 16 rows (positions 2p+half,
    // non-decreasing bag ids). Flush to gmem only at bag boundaries.
    float4 acc = make_float4(0.f, 0.f, 0.f, 0.f);
    int cur = __shfl_sync(FULL, seg, half);
    float* __restrict__ obase = out + f * D + hl * 4;

#pragma unroll
    for (int p = 0; p < 16; ++p) {
        const int s = __shfl_sync(FULL, seg, 2 * p + half);
        if (s != cur) {
            float* o = obase + (size_t)cur * (F * D);
            atomicAdd(o + 0, acc.x); atomicAdd(o + 1, acc.y);
            atomicAdd(o + 2, acc.z); atomicAdd(o + 3, acc.w);
            acc = make_float4(0.f, 0.f, 0.f, 0.f);
            cur = s;
        }
        acc.x += v[p].x; acc.y += v[p].y; acc.z += v[p].z; acc.w += v[p].w;
    }
    {
        float* o = obase + (size_t)cur * (F * D);
        atomicAdd(o + 0, acc.x); atomicAdd(o + 1, acc.y);
        atomicAdd(o + 2, acc.z); atomicAdd(o + 3, acc.w);
    }
}

extern "C" void kernel_launch(void* const* d_in, const int* in_sizes, int n_in,
                              void* d_out, int out_size)
{
    const float* tables  = (const float*)d_in[0];  // [F, N, D]
    const int*   values  = (const int*)  d_in[1];  // [F, T]
    const int*   offsets = (const int*)  d_in[2];  // [F, B+1]
    float*       out     = (float*)d_out;          // [B, F*D]

    // Zero the output (poisoned to 0xAA; empty bags must be 0).
    const int n4 = (B * F * D) / 4;                // 1,048,576 float4
    ebc_zero_kernel<<<(n4 + 511) / 512, 512>>>((float4*)out, n4);

    // Balanced gather: 40960 warps, 8 per block.
    const int total_warps = F * WPF;
    const int threads = 256;
    const int blocks = (total_warps * 32) / threads;  // 5120
    ebc_gather_kernel<<<blocks, threads>>>(tables, values, offsets, out);
}

// round 5
// speedup vs baseline: 1.3797x; 1.3797x over previous
#include <cuda_runtime.h>
#include <cuda_bf16.h>
#include <cstdint>

// EmbeddingBagCollection: F=8 tables [N=200000, D=64] f32, values [F, T=163840] i32,
// offsets [F, B+1=8193] i32. Output [B=8192, F*D=512] f32.
//
// One warp per (f, b) bag.
//  - 32 indices per chunk prefetched with one coalesced LDG, broadcast via shfl.
//  - Pair loading: half-warps take even/odd rows, each lane a float4
//    (16 lanes x 16B = 256B = one row) -> 2 rows per LDG.128.
//  - Fully-unrolled, per-pair PREDICATED 16-pair body: every needed load of a
//    chunk issues back-to-back (no serial remainder loop) -> up to 32 rows in
//    flight per warp with zero MLP=1 phases.
//  - __launch_bounds__(256,4) caps regs at 64 so occupancy stays at 32 warps/SM.
//  - shfl_xor(16) merges halves; lanes 0-15 store one coalesced 256B row.

static constexpr int F = 8;
static constexpr int B = 8192;
static constexpr int N = 200000;
static constexpr int D = 64;
static constexpr int T = 163840;
static constexpr unsigned FULL = 0xffffffffu;

__global__ __launch_bounds__(256, 4)
void ebc_pool_kernel(const float* __restrict__ tables,
                     const int*   __restrict__ values,
                     const int*   __restrict__ offsets,
                     float*       __restrict__ out)
{
    const int gwarp = (blockIdx.x * blockDim.x + threadIdx.x) >> 5;
    const int lane  = threadIdx.x & 31;
    if (gwarp >= F * B) return;

    const int f = gwarp >> 13;          // B = 8192 = 2^13
    const int b = gwarp & (B - 1);

    const int half = lane >> 4;         // 0: even rows, 1: odd rows
    const int hl   = lane & 15;         // float4 slot within a row

    const int* __restrict__ offs = offsets + f * (B + 1);
    const int start = __ldg(offs + b);
    const int end   = __ldg(offs + b + 1);

    const int* __restrict__ vals = values + (size_t)f * T;
    const float4* __restrict__ tab4 =
        reinterpret_cast<const float4*>(tables + (size_t)f * N * D);  // 16 float4 per row

    float4 acc = make_float4(0.f, 0.f, 0.f, 0.f);

    int i = start;
    while (i < end) {
        const int rem   = end - i;
        const int chunk = rem < 32 ? rem : 32;

        // Coalesced prefetch of the chunk's indices (clamped lane -> in bounds).
        const int src = lane < chunk ? lane : 0;
        const int idx = __ldg(vals + i + src);

        // All pair loads of this chunk, predicated, issued back-to-back.
#pragma unroll
        for (int p = 0; p < 16; ++p) {
            const int rp = 2 * p + half;            // row position in chunk
            const int r  = __shfl_sync(FULL, idx, rp & 31);
            if (rp < chunk) {
                const float4 v = __ldg(tab4 + (size_t)r * 16 + hl);
                acc.x += v.x; acc.y += v.y; acc.z += v.z; acc.w += v.w;
            }
        }
        i += chunk;
    }

    // Merge even/odd-row partial sums across half-warps.
    acc.x += __shfl_xor_sync(FULL, acc.x, 16);
    acc.y += __shfl_xor_sync(FULL, acc.y, 16);
    acc.z += __shfl_xor_sync(FULL, acc.z, 16);
    acc.w += __shfl_xor_sync(FULL, acc.w, 16);

    // Lanes 0-15 store one coalesced 256B row: out[b, f*D .. f*D+63].
    // (Runs for empty bags too -> writes required zeros over the poison.)
    if (lane < 16) {
        float4* __restrict__ o =
            reinterpret_cast<float4*>(out + (size_t)b * (F * D) + f * D);
        o[hl] = acc;
    }
}

extern "C" void kernel_launch(void* const* d_in, const int* in_sizes, int n_in,
                              void* d_out, int out_size)
{
    const float* tables  = (const float*)d_in[0];  // [F, N, D]
    const int*   values  = (const int*)  d_in[1];  // [F, T]
    const int*   offsets = (const int*)  d_in[2];  // [F, B+1]
    float*       out     = (float*)d_out;          // [B, F*D]

    const int total_warps = F * B;                 // 65536 bags
    const int threads = 256;                       // 8 warps/block
    const int blocks = (total_warps * 32 + threads - 1) / threads;  // 8192

    ebc_pool_kernel<<<blocks, threads>>>(tables, values, offsets, out);
}